// round 3
// baseline (speedup 1.0000x reference)
#include <cuda_runtime.h>
#include <math.h>

#define NN   50000
#define EE   800000
#define FIN  300
#define HID  128
#define NH   4
#define NC   9
#define NEG  0.2f

// ---------------- device scratch (no allocs allowed) ----------------
__device__ int   g_deg[NN];
__device__ int   g_rowptr[NN + 1];
__device__ int   g_wptr[NN];
__device__ int   g_bsum[64];
__device__ int   g_csr[EE];
__device__ int   g_is64;
__device__ float g_h[(size_t)NN * HID];
__device__ float g_act[(size_t)NN * HID];
__device__ float g_asrc[NN * NH];
__device__ float g_adst[NN * NH];
__device__ float g_h3[NN * NC];
__device__ float g_a3s[NN];
__device__ float g_a3d[NN];

#define FULLM 0xffffffffu

__device__ __forceinline__ float lrelu(float x) { return x > 0.f ? x : NEG * x; }
__device__ __forceinline__ float elu1(float x)  { return x > 0.f ? x : expm1f(x); }

__device__ __forceinline__ float warp_max(float v) {
#pragma unroll
    for (int o = 16; o > 0; o >>= 1) v = fmaxf(v, __shfl_xor_sync(FULLM, v, o));
    return v;
}
__device__ __forceinline__ float warp_sum(float v) {
#pragma unroll
    for (int o = 16; o > 0; o >>= 1) v += __shfl_xor_sync(FULLM, v, o);
    return v;
}

// edge index may be int64 (declared) or int32 (jax w/o x64). Detect once:
// sample 32 would-be high words; node ids < 50000 so int64 high words are 0.
__global__ void k_detect(const void* ei) {
    if (threadIdx.x == 0) {
        const int* p = (const int*)ei;
        int allz = 1;
#pragma unroll
        for (int i = 0; i < 32; i++) allz &= (p[2 * (i * 977) + 1] == 0);
        g_is64 = allz;
    }
}
__device__ __forceinline__ int edge_src(const void* ei, int e) {
    return g_is64 ? (int)((const long long*)ei)[e] : ((const int*)ei)[e];
}
__device__ __forceinline__ int edge_dst(const void* ei, int e) {
    return g_is64 ? (int)((const long long*)ei)[EE + e] : ((const int*)ei)[EE + e];
}

// ---------------- CSR build ----------------
__global__ void k_zero_deg() {
    int i = blockIdx.x * blockDim.x + threadIdx.x;
    if (i < NN) g_deg[i] = 0;
}
__global__ void k_hist(const void* ei) {
    int e = blockIdx.x * blockDim.x + threadIdx.x;
    if (e < EE) atomicAdd(&g_deg[edge_dst(ei, e)], 1);
}

#define SCAN_CHUNK 4096  // 256 threads x 16
#define SCAN_NB    ((NN + SCAN_CHUNK - 1) / SCAN_CHUNK)

__global__ void k_scan1() {
    __shared__ int sh[256];
    int t = threadIdx.x;
    int base = blockIdx.x * SCAN_CHUNK;
    int loc[16];
    int run = 0;
#pragma unroll
    for (int i = 0; i < 16; i++) {
        int idx = base + t * 16 + i;
        int v = (idx < NN) ? g_deg[idx] : 0;
        run += v;
        loc[i] = run;
    }
    sh[t] = run;
    __syncthreads();
    for (int off = 1; off < 256; off <<= 1) {
        int v = (t >= off) ? sh[t - off] : 0;
        __syncthreads();
        sh[t] += v;
        __syncthreads();
    }
    int pref = (t > 0) ? sh[t - 1] : 0;
    if (t == 255) g_bsum[blockIdx.x] = sh[255];
#pragma unroll
    for (int i = 0; i < 16; i++) {
        int idx = base + t * 16 + i;
        if (idx < NN) g_rowptr[idx + 1] = pref + loc[i];
    }
    if (blockIdx.x == 0 && t == 0) g_rowptr[0] = 0;
}
__global__ void k_scan2() {
    if (threadIdx.x == 0) {
        int run = 0;
        for (int b = 0; b < SCAN_NB; b++) {
            int x = g_bsum[b];
            g_bsum[b] = run;
            run += x;
        }
    }
}
// add block offsets AND initialize write pointers in one pass
__global__ void k_scan3() {
    int i = blockIdx.x * blockDim.x + threadIdx.x;
    if (i < NN) {
        int v = g_rowptr[i + 1] + g_bsum[i / SCAN_CHUNK];
        g_rowptr[i + 1] = v;
    }
}
__global__ void k_wptr() {
    int i = blockIdx.x * blockDim.x + threadIdx.x;
    if (i < NN) g_wptr[i] = g_rowptr[i];
}
__global__ void k_scatter(const void* ei) {
    int e = blockIdx.x * blockDim.x + threadIdx.x;
    if (e < EE) {
        int d = edge_dst(ei, e);
        int pos = atomicAdd(&g_wptr[d], 1);
        g_csr[pos] = edge_src(ei, e);
    }
}

// ---------------- SGEMM: g_h[M,128] = A[M,K] @ B[K,128] ----------------
// BM=128, BN=128, BK=8, 256 threads, 8x8 per-thread tile.
// 2-stage smem ping-pong with register staging: LDG(i+1) -> compute(i) ->
// STS(i+1) -> one __syncthreads per k-iteration.
#define BMP 132   // padded A-tile row to avoid STS bank conflicts
__global__ void __launch_bounds__(256) k_sgemm(const float* Aext, int useAct,
                                               const float* B, int M, int K) {
    __shared__ float As[2][8][BMP];
    __shared__ float Bs[2][8][128];
    const float* A = useAct ? (const float*)g_act : Aext;
    int tid = threadIdx.x;
    int tx = tid & 15;           // 0..15 -> col block of 8
    int ty = tid >> 4;           // 0..15 -> row block of 8
    int row0 = blockIdx.x * 128;
    float acc[8][8];
#pragma unroll
    for (int i = 0; i < 8; i++)
#pragma unroll
        for (int j = 0; j < 8; j++) acc[i][j] = 0.f;

    int a_row = tid >> 1;        // 0..127
    int a_k   = (tid & 1) * 4;   // 0 or 4
    int b_k   = tid >> 5;        // 0..7
    int b_n   = (tid & 31) * 4;
    int gr    = row0 + a_row;

    const int ntiles = (K + 7) / 8;

    // staging registers
    float4 avr, bvr;

    // --- load tile 0 ---
    {
        avr = make_float4(0.f, 0.f, 0.f, 0.f);
        if (gr < M) {
            int kc = a_k;
            if (kc + 4 <= K) {
                avr = *(const float4*)(A + (size_t)gr * K + kc);
            } else {
                float t[4] = {0.f, 0.f, 0.f, 0.f};
                for (int i = 0; i < 4; i++)
                    if (kc + i < K) t[i] = A[(size_t)gr * K + kc + i];
                avr = make_float4(t[0], t[1], t[2], t[3]);
            }
        }
        bvr = make_float4(0.f, 0.f, 0.f, 0.f);
        if (b_k < K) bvr = *(const float4*)(B + (size_t)b_k * 128 + b_n);
        As[0][a_k + 0][a_row] = avr.x;
        As[0][a_k + 1][a_row] = avr.y;
        As[0][a_k + 2][a_row] = avr.z;
        As[0][a_k + 3][a_row] = avr.w;
        *(float4*)(&Bs[0][b_k][b_n]) = bvr;
    }
    __syncthreads();

    for (int it = 0; it < ntiles; it++) {
        int buf = it & 1;
        // prefetch tile it+1 into registers (LDG issued, latency hidden by FMAs)
        if (it + 1 < ntiles) {
            int k0 = (it + 1) * 8;
            avr = make_float4(0.f, 0.f, 0.f, 0.f);
            if (gr < M) {
                int kc = k0 + a_k;
                if (kc + 4 <= K) {
                    avr = *(const float4*)(A + (size_t)gr * K + kc);
                } else {
                    float t[4] = {0.f, 0.f, 0.f, 0.f};
                    for (int i = 0; i < 4; i++)
                        if (kc + i < K) t[i] = A[(size_t)gr * K + kc + i];
                    avr = make_float4(t[0], t[1], t[2], t[3]);
                }
            }
            bvr = make_float4(0.f, 0.f, 0.f, 0.f);
            int kk = k0 + b_k;
            if (kk < K) bvr = *(const float4*)(B + (size_t)kk * 128 + b_n);
        }
        // compute tile it from smem[buf]
#pragma unroll
        for (int kk = 0; kk < 8; kk++) {
            float a[8], b[8];
            float4 v0 = *(float4*)(&As[buf][kk][ty * 8]);
            float4 v1 = *(float4*)(&As[buf][kk][ty * 8 + 4]);
            a[0] = v0.x; a[1] = v0.y; a[2] = v0.z; a[3] = v0.w;
            a[4] = v1.x; a[5] = v1.y; a[6] = v1.z; a[7] = v1.w;
            float4 w0 = *(float4*)(&Bs[buf][kk][tx * 8]);
            float4 w1 = *(float4*)(&Bs[buf][kk][tx * 8 + 4]);
            b[0] = w0.x; b[1] = w0.y; b[2] = w0.z; b[3] = w0.w;
            b[4] = w1.x; b[5] = w1.y; b[6] = w1.z; b[7] = w1.w;
#pragma unroll
            for (int i = 0; i < 8; i++)
#pragma unroll
                for (int j = 0; j < 8; j++) acc[i][j] += a[i] * b[j];
        }
        // stage tile it+1 into the other smem buffer
        if (it + 1 < ntiles) {
            int nb = buf ^ 1;
            As[nb][a_k + 0][a_row] = avr.x;
            As[nb][a_k + 1][a_row] = avr.y;
            As[nb][a_k + 2][a_row] = avr.z;
            As[nb][a_k + 3][a_row] = avr.w;
            *(float4*)(&Bs[nb][b_k][b_n]) = bvr;
            __syncthreads();
        }
    }

#pragma unroll
    for (int i = 0; i < 8; i++) {
        int gm = row0 + ty * 8 + i;
        if (gm < M) {
            float4 v0 = make_float4(acc[i][0], acc[i][1], acc[i][2], acc[i][3]);
            float4 v1 = make_float4(acc[i][4], acc[i][5], acc[i][6], acc[i][7]);
            *(float4*)(&g_h[(size_t)gm * 128 + tx * 8])     = v0;
            *(float4*)(&g_h[(size_t)gm * 128 + tx * 8 + 4]) = v1;
        }
    }
}

// ---------------- per-node attention scores a_src/a_dst (layers 1,2) ----------
// warp per node; lane covers 4 consecutive features; head = lane>>3.
__global__ void k_attscore(const float* att_s, const float* att_d) {
    int n = blockIdx.x * 8 + (threadIdx.x >> 5);
    if (n >= NN) return;
    int lane = threadIdx.x & 31;
    int c0 = lane * 4;
    float4 hv = *(const float4*)(g_h + (size_t)n * 128 + c0);
    float4 sv = *(const float4*)(att_s + c0);
    float4 dv = *(const float4*)(att_d + c0);
    float ps = hv.x * sv.x + hv.y * sv.y + hv.z * sv.z + hv.w * sv.w;
    float pd = hv.x * dv.x + hv.y * dv.y + hv.z * dv.z + hv.w * dv.w;
#pragma unroll
    for (int o = 1; o < 8; o <<= 1) {
        ps += __shfl_xor_sync(FULLM, ps, o);
        pd += __shfl_xor_sync(FULLM, pd, o);
    }
    if ((lane & 7) == 0) {
        int head = lane >> 3;
        g_asrc[n * 4 + head] = ps;
        g_adst[n * 4 + head] = pd;
    }
}

// ---------------- attention + aggregation + bias + ELU (layers 1,2) ----------
// warp per node; gather over CSR; out -> g_act. No shuffles in the hot loop:
// each lane keeps its own head's (m, 1/denom, a_dst) and recomputes alpha.
__global__ void __launch_bounds__(256) k_attn(const float* bias) {
    int n = blockIdx.x * 8 + (threadIdx.x >> 5);
    if (n >= NN) return;
    int lane = threadIdx.x & 31;
    int s0 = g_rowptr[n], s1 = g_rowptr[n + 1];
    float4 adv = *(const float4*)(g_adst + 4 * n);

    // pass 1: per-head max (lane-strided, vectorized asrc reads)
    float m0 = -1e30f, m1 = -1e30f, m2 = -1e30f, m3 = -1e30f;
    for (int i = s0 + lane; i < s1; i += 32) {
        int s = g_csr[i];
        float4 av = *(const float4*)(g_asrc + 4 * s);
        m0 = fmaxf(m0, lrelu(av.x + adv.x));
        m1 = fmaxf(m1, lrelu(av.y + adv.y));
        m2 = fmaxf(m2, lrelu(av.z + adv.z));
        m3 = fmaxf(m3, lrelu(av.w + adv.w));
    }
    m0 = warp_max(m0); m1 = warp_max(m1); m2 = warp_max(m2); m3 = warp_max(m3);

    // pass 2: per-head denom
    float d0 = 0.f, d1 = 0.f, d2 = 0.f, d3 = 0.f;
    for (int i = s0 + lane; i < s1; i += 32) {
        int s = g_csr[i];
        float4 av = *(const float4*)(g_asrc + 4 * s);
        d0 += __expf(lrelu(av.x + adv.x) - m0);
        d1 += __expf(lrelu(av.y + adv.y) - m1);
        d2 += __expf(lrelu(av.z + adv.z) - m2);
        d3 += __expf(lrelu(av.w + adv.w) - m3);
    }
    d0 = warp_sum(d0); d1 = warp_sum(d1); d2 = warp_sum(d2); d3 = warp_sum(d3);

    // each lane selects its own head's constants
    int head = lane >> 3;
    float mh  = (head == 0) ? m0 : (head == 1) ? m1 : (head == 2) ? m2 : m3;
    float dh  = (head == 0) ? d0 : (head == 1) ? d1 : (head == 2) ? d2 : d3;
    float adh = (head == 0) ? adv.x : (head == 1) ? adv.y : (head == 2) ? adv.z : adv.w;
    float idh = 1.f / dh;

    // pass 3: weighted feature gather — uniform edge loop, no shuffles.
    float4 acc = make_float4(0.f, 0.f, 0.f, 0.f);
#pragma unroll 2
    for (int i = s0; i < s1; i++) {
        int s = g_csr[i];                          // uniform broadcast load
        float a = __ldg(g_asrc + 4 * s + head);    // one 16B sector per warp
        float al = __expf(lrelu(a + adh) - mh) * idh;
        float4 hv = *(const float4*)(g_h + (size_t)s * 128 + (lane << 2));
        acc.x += al * hv.x;
        acc.y += al * hv.y;
        acc.z += al * hv.z;
        acc.w += al * hv.w;
    }
    float4 bv = *(const float4*)(bias + (lane << 2));
    float4 o;
    o.x = elu1(acc.x + bv.x);
    o.y = elu1(acc.y + bv.y);
    o.z = elu1(acc.z + bv.z);
    o.w = elu1(acc.w + bv.w);
    *(float4*)(g_act + (size_t)n * 128 + (lane << 2)) = o;
}

// ---------------- layer 3 GEMM: h3 = g_act @ W3 (+att scores) ----------------
__global__ void __launch_bounds__(256) k_gemm3(const float* W3, const float* as3,
                                               const float* ad3) {
    __shared__ float sW[128 * NC];
    int tid = threadIdx.x;
    for (int i = tid; i < 128 * NC; i += 256) sW[i] = W3[i];
    __syncthreads();
    int n = blockIdx.x * 8 + (tid >> 5);
    if (n >= NN) return;
    int lane = tid & 31;
    float4 hv = *(const float4*)(g_act + (size_t)n * 128 + lane * 4);
    float p[NC];
#pragma unroll
    for (int j = 0; j < NC; j++) {
        int k = lane * 4;
        p[j] = hv.x * sW[(k + 0) * NC + j] + hv.y * sW[(k + 1) * NC + j] +
               hv.z * sW[(k + 2) * NC + j] + hv.w * sW[(k + 3) * NC + j];
    }
#pragma unroll
    for (int j = 0; j < NC; j++) p[j] = warp_sum(p[j]);
    if (lane == 0) {
        float as_ = 0.f, ad_ = 0.f;
#pragma unroll
        for (int j = 0; j < NC; j++) {
            g_h3[n * NC + j] = p[j];
            as_ += p[j] * as3[j];
            ad_ += p[j] * ad3[j];
        }
        g_a3s[n] = as_;
        g_a3d[n] = ad_;
    }
}

// ---------------- layer 3 attention + bias + ELU + log_softmax ----------------
__global__ void __launch_bounds__(256) k_attn3(const float* b3, float* out) {
    int n = blockIdx.x * 8 + (threadIdx.x >> 5);
    if (n >= NN) return;
    int lane = threadIdx.x & 31;
    int s0 = g_rowptr[n], s1 = g_rowptr[n + 1];
    float ad = g_a3d[n];

    float m = -1e30f;
    for (int i = s0 + lane; i < s1; i += 32)
        m = fmaxf(m, lrelu(g_a3s[g_csr[i]] + ad));
    m = warp_max(m);

    float den = 0.f;
    for (int i = s0 + lane; i < s1; i += 32)
        den += __expf(lrelu(g_a3s[g_csr[i]] + ad) - m);
    den = warp_sum(den);
    float iden = 1.f / den;

    float acc[NC];
#pragma unroll
    for (int j = 0; j < NC; j++) acc[j] = 0.f;
    for (int i = s0 + lane; i < s1; i += 32) {
        int s = g_csr[i];
        float al = __expf(lrelu(g_a3s[s] + ad) - m) * iden;
#pragma unroll
        for (int j = 0; j < NC; j++) acc[j] += al * g_h3[s * NC + j];
    }
#pragma unroll
    for (int j = 0; j < NC; j++) acc[j] = warp_sum(acc[j]);

    if (lane == 0) {
        float v[NC];
        float mm = -1e30f;
#pragma unroll
        for (int j = 0; j < NC; j++) {
            v[j] = elu1(acc[j] + b3[j]);
            mm = fmaxf(mm, v[j]);
        }
        float ss = 0.f;
#pragma unroll
        for (int j = 0; j < NC; j++) ss += __expf(v[j] - mm);
        float ls = logf(ss);
#pragma unroll
        for (int j = 0; j < NC; j++) out[n * NC + j] = v[j] - mm - ls;
    }
}

// ---------------- launch ----------------
extern "C" void kernel_launch(void* const* d_in, const int* in_sizes, int n_in,
                              void* d_out, int out_size) {
    const float* x   = (const float*)d_in[0];
    const void*  ei  = d_in[1];
    const float* W1  = (const float*)d_in[2];
    const float* as1 = (const float*)d_in[3];
    const float* ad1 = (const float*)d_in[4];
    const float* b1  = (const float*)d_in[5];
    const float* W2  = (const float*)d_in[6];
    const float* as2 = (const float*)d_in[7];
    const float* ad2 = (const float*)d_in[8];
    const float* b2  = (const float*)d_in[9];
    const float* W3  = (const float*)d_in[10];
    const float* as3 = (const float*)d_in[11];
    const float* ad3 = (const float*)d_in[12];
    const float* b3  = (const float*)d_in[13];
    float* out = (float*)d_out;

    const int NB_N = (NN + 255) / 256;
    const int NB_E = (EE + 255) / 256;
    const int NB_W = (NN + 7) / 8;          // warp-per-node kernels, 256 tpb
    const int NB_G = (NN + 127) / 128;      // sgemm blocks

    // CSR build (reused by all 3 layers)
    k_detect<<<1, 32>>>(ei);
    k_zero_deg<<<NB_N, 256>>>();
    k_hist<<<NB_E, 256>>>(ei);
    k_scan1<<<SCAN_NB, 256>>>();
    k_scan2<<<1, 32>>>();
    k_scan3<<<NB_N, 256>>>();
    k_wptr<<<NB_N, 256>>>();
    k_scatter<<<NB_E, 256>>>(ei);

    // layer 1
    k_sgemm<<<NB_G, 256>>>(x, 0, W1, NN, FIN);
    k_attscore<<<NB_W, 256>>>(as1, ad1);
    k_attn<<<NB_W, 256>>>(b1);

    // layer 2
    k_sgemm<<<NB_G, 256>>>(nullptr, 1, W2, NN, HID);
    k_attscore<<<NB_W, 256>>>(as2, ad2);
    k_attn<<<NB_W, 256>>>(b2);

    // layer 3
    k_gemm3<<<NB_W, 256>>>(W3, as3, ad3);
    k_attn3<<<NB_W, 256>>>(b3, out);
}

// round 14
// speedup vs baseline: 1.0432x; 1.0432x over previous
#include <cuda_runtime.h>
#include <math.h>

#define NN   50000
#define EE   800000
#define FIN  300
#define HID  128
#define NH   4
#define NC   9
#define NEG  0.2f

typedef unsigned long long u64;

// ---------------- device scratch (no allocs allowed) ----------------
__device__ int   g_deg[NN];
__device__ int   g_rowptr[NN + 1];
__device__ int   g_wptr[NN];
__device__ int   g_bsum[64];
__device__ int   g_csr[EE];
__device__ int   g_is64;
__device__ float g_h[(size_t)NN * HID];
__device__ float g_act[(size_t)NN * HID];
__device__ float g_asrc[NN * NH];
__device__ float g_adst[NN * NH];
__device__ float g_h3[NN * NC];
__device__ float g_a3s[NN];
__device__ float g_a3d[NN];

#define FULLM 0xffffffffu

__device__ __forceinline__ float lrelu(float x) { return x > 0.f ? x : NEG * x; }
__device__ __forceinline__ float elu1(float x)  { return x > 0.f ? x : expm1f(x); }

__device__ __forceinline__ float warp_max(float v) {
#pragma unroll
    for (int o = 16; o > 0; o >>= 1) v = fmaxf(v, __shfl_xor_sync(FULLM, v, o));
    return v;
}
__device__ __forceinline__ float warp_sum(float v) {
#pragma unroll
    for (int o = 16; o > 0; o >>= 1) v += __shfl_xor_sync(FULLM, v, o);
    return v;
}

// ---- packed fp32x2 helpers (Blackwell) ----
__device__ __forceinline__ void ffma2(u64& d, u64 a, u64 b) {
    asm("fma.rn.f32x2 %0, %1, %2, %0;" : "+l"(d) : "l"(a), "l"(b));
}
__device__ __forceinline__ u64 dup2(float x) {
    u64 r;
    asm("mov.b64 %0, {%1, %1};" : "=l"(r) : "f"(x));
    return r;
}
__device__ __forceinline__ void unpack2(u64 v, float& lo, float& hi) {
    asm("mov.b64 {%0, %1}, %2;" : "=f"(lo), "=f"(hi) : "l"(v));
}

// online-softmax lane update: m' = max(m,e); d = d*exp(m-m') + exp(e-m')
__device__ __forceinline__ void osm_update(float e, float& m, float& d) {
    float mn = fmaxf(m, e);
    d = d * __expf(m - mn) + __expf(e - mn);
    m = mn;
}
// warp-combine lane-partial (m,d) -> warp (m,d)
__device__ __forceinline__ void osm_combine(float& m, float& d) {
    float M = warp_max(m);
    d = warp_sum(d * __expf(m - M));
    m = M;
}

// fused: zero g_deg (all blocks) + dtype probe (block 0, thread 0).
// g_is64 is only read by LATER launches (stream order guarantees visibility).
// edge index may be int64 (declared) or int32 (jax w/o x64): node ids < 50000
// so int64 high words are all zero; sample 32 of them.
__global__ void k_detect_zero(const void* ei) {
    int i = blockIdx.x * blockDim.x + threadIdx.x;
    if (i < NN) g_deg[i] = 0;
    if (i == 0) {
        const int* p = (const int*)ei;
        int allz = 1;
#pragma unroll
        for (int k = 0; k < 32; k++) allz &= (p[2 * (k * 977) + 1] == 0);
        g_is64 = allz;
    }
}
__device__ __forceinline__ int edge_src(const void* ei, int e) {
    return g_is64 ? (int)((const long long*)ei)[e] : ((const int*)ei)[e];
}
__device__ __forceinline__ int edge_dst(const void* ei, int e) {
    return g_is64 ? (int)((const long long*)ei)[EE + e] : ((const int*)ei)[EE + e];
}

// ---------------- CSR build ----------------
__global__ void k_hist(const void* ei) {
    int e = blockIdx.x * blockDim.x + threadIdx.x;
    if (e < EE) atomicAdd(&g_deg[edge_dst(ei, e)], 1);
}

#define SCAN_CHUNK 4096  // 256 threads x 16
#define SCAN_NB    ((NN + SCAN_CHUNK - 1) / SCAN_CHUNK)

__global__ void k_scan1() {
    __shared__ int sh[256];
    int t = threadIdx.x;
    int base = blockIdx.x * SCAN_CHUNK;
    int loc[16];
    int run = 0;
#pragma unroll
    for (int i = 0; i < 16; i++) {
        int idx = base + t * 16 + i;
        int v = (idx < NN) ? g_deg[idx] : 0;
        run += v;
        loc[i] = run;
    }
    sh[t] = run;
    __syncthreads();
    for (int off = 1; off < 256; off <<= 1) {
        int v = (t >= off) ? sh[t - off] : 0;
        __syncthreads();
        sh[t] += v;
        __syncthreads();
    }
    int pref = (t > 0) ? sh[t - 1] : 0;
    if (t == 255) g_bsum[blockIdx.x] = sh[255];
#pragma unroll
    for (int i = 0; i < 16; i++) {
        int idx = base + t * 16 + i;
        if (idx < NN) g_rowptr[idx + 1] = pref + loc[i];
    }
    if (blockIdx.x == 0 && t == 0) g_rowptr[0] = 0;
}
__global__ void k_scan2() {
    if (threadIdx.x == 0) {
        int run = 0;
        for (int b = 0; b < SCAN_NB; b++) {
            int x = g_bsum[b];
            g_bsum[b] = run;
            run += x;
        }
    }
}
// add block offsets AND mirror final rowptr into wptr (one writer per address).
__global__ void k_scan3() {
    int i = blockIdx.x * blockDim.x + threadIdx.x;
    if (i < NN) {
        int v = g_rowptr[i + 1] + g_bsum[i / SCAN_CHUNK];
        g_rowptr[i + 1] = v;
        if (i + 1 < NN) g_wptr[i + 1] = v;
        if (i == 0) g_wptr[0] = 0;
    }
}
__global__ void k_scatter(const void* ei) {
    int e = blockIdx.x * blockDim.x + threadIdx.x;
    if (e < EE) {
        int d = edge_dst(ei, e);
        int pos = atomicAdd(&g_wptr[d], 1);
        g_csr[pos] = edge_src(ei, e);
    }
}

// ---------------- SGEMM: g_h[M,128] = A[M,K] @ B[K,128] ----------------
// BM=128, BN=128, BK=8, 256 threads, 8x8 per-thread tile.
// 2-stage smem ping-pong + packed fma.rn.f32x2 inner loop (row-paired accs):
// 32 FFMA2 + 8 dup-MOV per k-step replaces 64 scalar FFMA -> 2x fma-pipe.
#define BMP 132   // padded A-tile row to avoid STS bank conflicts
__global__ void __launch_bounds__(256) k_sgemm(const float* Aext, int useAct,
                                               const float* B, int M, int K) {
    __shared__ __align__(16) float As[2][8][BMP];
    __shared__ __align__(16) float Bs[2][8][128];
    const float* A = useAct ? (const float*)g_act : Aext;
    int tid = threadIdx.x;
    int tx = tid & 15;           // 0..15 -> col block of 8
    int ty = tid >> 4;           // 0..15 -> row block of 8
    int row0 = blockIdx.x * 128;

    // packed accumulators: accp[ip][j] = (acc[2ip][j], acc[2ip+1][j])
    u64 accp[4][8];
#pragma unroll
    for (int i = 0; i < 4; i++)
#pragma unroll
        for (int j = 0; j < 8; j++) accp[i][j] = 0ull;

    int a_row = tid >> 1;        // 0..127
    int a_k   = (tid & 1) * 4;   // 0 or 4
    int b_k   = tid >> 5;        // 0..7
    int b_n   = (tid & 31) * 4;
    int gr    = row0 + a_row;

    const int ntiles = (K + 7) / 8;

    float4 avr, bvr;

    // --- load tile 0 ---
    {
        avr = make_float4(0.f, 0.f, 0.f, 0.f);
        if (gr < M) {
            int kc = a_k;
            if (kc + 4 <= K) {
                avr = *(const float4*)(A + (size_t)gr * K + kc);
            } else {
                float t[4] = {0.f, 0.f, 0.f, 0.f};
                for (int i = 0; i < 4; i++)
                    if (kc + i < K) t[i] = A[(size_t)gr * K + kc + i];
                avr = make_float4(t[0], t[1], t[2], t[3]);
            }
        }
        bvr = make_float4(0.f, 0.f, 0.f, 0.f);
        if (b_k < K) bvr = *(const float4*)(B + (size_t)b_k * 128 + b_n);
        As[0][a_k + 0][a_row] = avr.x;
        As[0][a_k + 1][a_row] = avr.y;
        As[0][a_k + 2][a_row] = avr.z;
        As[0][a_k + 3][a_row] = avr.w;
        *(float4*)(&Bs[0][b_k][b_n]) = bvr;
    }
    __syncthreads();

    for (int it = 0; it < ntiles; it++) {
        int buf = it & 1;
        // prefetch tile it+1 into registers (LDG latency hidden by FMAs)
        if (it + 1 < ntiles) {
            int k0 = (it + 1) * 8;
            avr = make_float4(0.f, 0.f, 0.f, 0.f);
            if (gr < M) {
                int kc = k0 + a_k;
                if (kc + 4 <= K) {
                    avr = *(const float4*)(A + (size_t)gr * K + kc);
                } else {
                    float t[4] = {0.f, 0.f, 0.f, 0.f};
                    for (int i = 0; i < 4; i++)
                        if (kc + i < K) t[i] = A[(size_t)gr * K + kc + i];
                    avr = make_float4(t[0], t[1], t[2], t[3]);
                }
            }
            bvr = make_float4(0.f, 0.f, 0.f, 0.f);
            int kk = k0 + b_k;
            if (kk < K) bvr = *(const float4*)(B + (size_t)kk * 128 + b_n);
        }
        // compute tile it from smem[buf] with packed FMAs
#pragma unroll
        for (int kk = 0; kk < 8; kk++) {
            // A row-pairs: adjacent floats out of LDS.128 -> free u64 pairs
            float4 v0 = *(float4*)(&As[buf][kk][ty * 8]);
            float4 v1 = *(float4*)(&As[buf][kk][ty * 8 + 4]);
            u64 ap[4];
            ap[0] = *(u64*)&v0.x;  // (a0,a1)
            ap[1] = *(u64*)&v0.z;  // (a2,a3)
            ap[2] = *(u64*)&v1.x;  // (a4,a5)
            ap[3] = *(u64*)&v1.z;  // (a6,a7)
            float4 w0 = *(float4*)(&Bs[buf][kk][tx * 8]);
            float4 w1 = *(float4*)(&Bs[buf][kk][tx * 8 + 4]);
            u64 bp[8];
            bp[0] = dup2(w0.x); bp[1] = dup2(w0.y);
            bp[2] = dup2(w0.z); bp[3] = dup2(w0.w);
            bp[4] = dup2(w1.x); bp[5] = dup2(w1.y);
            bp[6] = dup2(w1.z); bp[7] = dup2(w1.w);
#pragma unroll
            for (int i = 0; i < 4; i++)
#pragma unroll
                for (int j = 0; j < 8; j++) ffma2(accp[i][j], ap[i], bp[j]);
        }
        // stage tile it+1 into the other smem buffer
        if (it + 1 < ntiles) {
            int nb = buf ^ 1;
            As[nb][a_k + 0][a_row] = avr.x;
            As[nb][a_k + 1][a_row] = avr.y;
            As[nb][a_k + 2][a_row] = avr.z;
            As[nb][a_k + 3][a_row] = avr.w;
            *(float4*)(&Bs[nb][b_k][b_n]) = bvr;
            __syncthreads();
        }
    }

    // epilogue: unpack row pairs and store
#pragma unroll
    for (int ip = 0; ip < 4; ip++) {
        float lo[8], hi[8];
#pragma unroll
        for (int j = 0; j < 8; j++) unpack2(accp[ip][j], lo[j], hi[j]);
        int gm0 = row0 + ty * 8 + 2 * ip;
        if (gm0 < M) {
            *(float4*)(&g_h[(size_t)gm0 * 128 + tx * 8])     = make_float4(lo[0], lo[1], lo[2], lo[3]);
            *(float4*)(&g_h[(size_t)gm0 * 128 + tx * 8 + 4]) = make_float4(lo[4], lo[5], lo[6], lo[7]);
        }
        if (gm0 + 1 < M) {
            *(float4*)(&g_h[(size_t)(gm0 + 1) * 128 + tx * 8])     = make_float4(hi[0], hi[1], hi[2], hi[3]);
            *(float4*)(&g_h[(size_t)(gm0 + 1) * 128 + tx * 8 + 4]) = make_float4(hi[4], hi[5], hi[6], hi[7]);
        }
    }
}

// ---------------- per-node attention scores a_src/a_dst (layers 1,2) ----------
// warp per node; lane covers 4 consecutive features; head = lane>>3.
__global__ void k_attscore(const float* att_s, const float* att_d) {
    int n = blockIdx.x * 8 + (threadIdx.x >> 5);
    if (n >= NN) return;
    int lane = threadIdx.x & 31;
    int c0 = lane * 4;
    float4 hv = *(const float4*)(g_h + (size_t)n * 128 + c0);
    float4 sv = *(const float4*)(att_s + c0);
    float4 dv = *(const float4*)(att_d + c0);
    float ps = hv.x * sv.x + hv.y * sv.y + hv.z * sv.z + hv.w * sv.w;
    float pd = hv.x * dv.x + hv.y * dv.y + hv.z * dv.z + hv.w * dv.w;
#pragma unroll
    for (int o = 1; o < 8; o <<= 1) {
        ps += __shfl_xor_sync(FULLM, ps, o);
        pd += __shfl_xor_sync(FULLM, pd, o);
    }
    if ((lane & 7) == 0) {
        int head = lane >> 3;
        g_asrc[n * 4 + head] = ps;
        g_adst[n * 4 + head] = pd;
    }
}

// ---------------- attention + aggregation + bias + ELU (layers 1,2) ----------
// warp per node; gather over CSR; out -> g_act.
// Pass A: online softmax (max+denom in ONE csr pass). Pass B: weighted gather.
__global__ void __launch_bounds__(256) k_attn(const float* bias) {
    int n = blockIdx.x * 8 + (threadIdx.x >> 5);
    if (n >= NN) return;
    int lane = threadIdx.x & 31;
    int s0 = g_rowptr[n], s1 = g_rowptr[n + 1];
    float4 adv = *(const float4*)(g_adst + 4 * n);

    // pass A: per-head online (m, d), lane-strided
    float m0 = -1e30f, m1 = -1e30f, m2 = -1e30f, m3 = -1e30f;
    float d0 = 0.f, d1 = 0.f, d2 = 0.f, d3 = 0.f;
    for (int i = s0 + lane; i < s1; i += 32) {
        int s = g_csr[i];
        float4 av = *(const float4*)(g_asrc + 4 * s);
        osm_update(lrelu(av.x + adv.x), m0, d0);
        osm_update(lrelu(av.y + adv.y), m1, d1);
        osm_update(lrelu(av.z + adv.z), m2, d2);
        osm_update(lrelu(av.w + adv.w), m3, d3);
    }
    osm_combine(m0, d0); osm_combine(m1, d1);
    osm_combine(m2, d2); osm_combine(m3, d3);

    // each lane selects its own head's constants
    int head = lane >> 3;
    float mh  = (head == 0) ? m0 : (head == 1) ? m1 : (head == 2) ? m2 : m3;
    float dh  = (head == 0) ? d0 : (head == 1) ? d1 : (head == 2) ? d2 : d3;
    float adh = (head == 0) ? adv.x : (head == 1) ? adv.y : (head == 2) ? adv.z : adv.w;
    float idh = 1.f / dh;

    // pass B: weighted feature gather — uniform edge loop, no shuffles.
    float4 acc = make_float4(0.f, 0.f, 0.f, 0.f);
#pragma unroll 4
    for (int i = s0; i < s1; i++) {
        int s = g_csr[i];                          // uniform broadcast load
        float a = __ldg(g_asrc + 4 * s + head);    // one 16B sector per warp
        float al = __expf(lrelu(a + adh) - mh) * idh;
        float4 hv = *(const float4*)(g_h + (size_t)s * 128 + (lane << 2));
        acc.x += al * hv.x;
        acc.y += al * hv.y;
        acc.z += al * hv.z;
        acc.w += al * hv.w;
    }
    float4 bv = *(const float4*)(bias + (lane << 2));
    float4 o;
    o.x = elu1(acc.x + bv.x);
    o.y = elu1(acc.y + bv.y);
    o.z = elu1(acc.z + bv.z);
    o.w = elu1(acc.w + bv.w);
    *(float4*)(g_act + (size_t)n * 128 + (lane << 2)) = o;
}

// ---------------- layer 3 GEMM: h3 = g_act @ W3 (+att scores) ----------------
__global__ void __launch_bounds__(256) k_gemm3(const float* W3, const float* as3,
                                               const float* ad3) {
    __shared__ float sW[128 * NC];
    int tid = threadIdx.x;
    for (int i = tid; i < 128 * NC; i += 256) sW[i] = W3[i];
    __syncthreads();
    int n = blockIdx.x * 8 + (tid >> 5);
    if (n >= NN) return;
    int lane = tid & 31;
    float4 hv = *(const float4*)(g_act + (size_t)n * 128 + lane * 4);
    float p[NC];
#pragma unroll
    for (int j = 0; j < NC; j++) {
        int k = lane * 4;
        p[j] = hv.x * sW[(k + 0) * NC + j] + hv.y * sW[(k + 1) * NC + j] +
               hv.z * sW[(k + 2) * NC + j] + hv.w * sW[(k + 3) * NC + j];
    }
#pragma unroll
    for (int j = 0; j < NC; j++) p[j] = warp_sum(p[j]);
    if (lane == 0) {
        float as_ = 0.f, ad_ = 0.f;
#pragma unroll
        for (int j = 0; j < NC; j++) {
            g_h3[n * NC + j] = p[j];
            as_ += p[j] * as3[j];
            ad_ += p[j] * ad3[j];
        }
        g_a3s[n] = as_;
        g_a3d[n] = ad_;
    }
}

// ---------------- layer 3 attention + bias + ELU + log_softmax ----------------
__global__ void __launch_bounds__(256) k_attn3(const float* b3, float* out) {
    int n = blockIdx.x * 8 + (threadIdx.x >> 5);
    if (n >= NN) return;
    int lane = threadIdx.x & 31;
    int s0 = g_rowptr[n], s1 = g_rowptr[n + 1];
    float ad = g_a3d[n];

    // online softmax over incoming edges (single csr pass)
    float m = -1e30f, den = 0.f;
    for (int i = s0 + lane; i < s1; i += 32)
        osm_update(lrelu(g_a3s[g_csr[i]] + ad), m, den);
    osm_combine(m, den);
    float iden = 1.f / den;

    float acc[NC];
#pragma unroll
    for (int j = 0; j < NC; j++) acc[j] = 0.f;
    for (int i = s0 + lane; i < s1; i += 32) {
        int s = g_csr[i];
        float al = __expf(lrelu(g_a3s[s] + ad) - m) * iden;
#pragma unroll
        for (int j = 0; j < NC; j++) acc[j] += al * g_h3[s * NC + j];
    }
#pragma unroll
    for (int j = 0; j < NC; j++) acc[j] = warp_sum(acc[j]);

    if (lane == 0) {
        float v[NC];
        float mm = -1e30f;
#pragma unroll
        for (int j = 0; j < NC; j++) {
            v[j] = elu1(acc[j] + b3[j]);
            mm = fmaxf(mm, v[j]);
        }
        float ss = 0.f;
#pragma unroll
        for (int j = 0; j < NC; j++) ss += __expf(v[j] - mm);
        float ls = logf(ss);
#pragma unroll
        for (int j = 0; j < NC; j++) out[n * NC + j] = v[j] - mm - ls;
    }
}

// ---------------- launch ----------------
extern "C" void kernel_launch(void* const* d_in, const int* in_sizes, int n_in,
                              void* d_out, int out_size) {
    const float* x   = (const float*)d_in[0];
    const void*  ei  = d_in[1];
    const float* W1  = (const float*)d_in[2];
    const float* as1 = (const float*)d_in[3];
    const float* ad1 = (const float*)d_in[4];
    const float* b1  = (const float*)d_in[5];
    const float* W2  = (const float*)d_in[6];
    const float* as2 = (const float*)d_in[7];
    const float* ad2 = (const float*)d_in[8];
    const float* b2  = (const float*)d_in[9];
    const float* W3  = (const float*)d_in[10];
    const float* as3 = (const float*)d_in[11];
    const float* ad3 = (const float*)d_in[12];
    const float* b3  = (const float*)d_in[13];
    float* out = (float*)d_out;

    const int NB_N = (NN + 255) / 256;
    const int NB_E = (EE + 255) / 256;
    const int NB_W = (NN + 7) / 8;          // warp-per-node kernels, 256 tpb
    const int NB_G = (NN + 127) / 128;      // sgemm blocks

    // CSR build (reused by all 3 layers)
    k_detect_zero<<<NB_N, 256>>>(ei);
    k_hist<<<NB_E, 256>>>(ei);
    k_scan1<<<SCAN_NB, 256>>>();
    k_scan2<<<1, 32>>>();
    k_scan3<<<NB_N, 256>>>();
    k_scatter<<<NB_E, 256>>>(ei);

    // layer 1
    k_sgemm<<<NB_G, 256>>>(x, 0, W1, NN, FIN);
    k_attscore<<<NB_W, 256>>>(as1, ad1);
    k_attn<<<NB_W, 256>>>(b1);

    // layer 2
    k_sgemm<<<NB_G, 256>>>(nullptr, 1, W2, NN, HID);
    k_attscore<<<NB_W, 256>>>(as2, ad2);
    k_attn<<<NB_W, 256>>>(b2);

    // layer 3
    k_gemm3<<<NB_W, 256>>>(W3, as3, ad3);
    k_attn3<<<NB_W, 256>>>(b3, out);
}